// round 14
// baseline (speedup 1.0000x reference)
#include <cuda_runtime.h>
#include <mma.h>
#include <math.h>
#include <stdint.h>

#define SEQ   128
#define BATCH 64
#define HID   1024
#define VOCAB 10000
#define NPAD  10112              /* 79 * 128 */
#define TB    (SEQ*BATCH)        /* 8192 */
#define SB    (BATCH*HID)        /* 65536 */
#define NCTA  128                /* persistent scan grid (<= 148 SMs) */

// ---------------- device scratch (no allocations allowed) -------------------
__device__ float g_Xp[TB*HID];          // RAW x_t @ Wx0^T (no bias), all steps
__device__ float g_H1[(SEQ+1)*SB];      // slot t = h1 entering step t
__device__ float g_h0[2*SB];            // h0 ping-pong
__device__ float g_Wc[HID*HID];         // Wx1 @ Wy0
__device__ float g_Wy0T[HID*HID];       // Wy0 transposed
__device__ float g_cb1[HID];            // bh1 + Wx1 @ by0
__device__ float g_Wy1p[NPAD*HID];      // zero-padded Wy1

// persistent-scan barrier state
__device__ unsigned g_bar_count;
__device__ volatile unsigned g_bar_gen;

// ---------------- XLA EmitFastTanh, FMA-contracted (verified passing) --------
__device__ __forceinline__ float xla_tanh(float x)
{
    const float kClamp = 7.90531110763549805f;
    float xc = fminf(fmaxf(x, -kClamp), kClamp);
    float x2 = __fmul_rn(xc, xc);
    float n = __fmaf_rn(x2, -2.76076847742355e-16f, 2.00018790482477e-13f);
    n = __fmaf_rn(x2, n, -8.60467152213735e-11f);
    n = __fmaf_rn(x2, n,  5.12229709037114e-08f);
    n = __fmaf_rn(x2, n,  1.48572235717979e-05f);
    n = __fmaf_rn(x2, n,  6.37261928875436e-04f);
    n = __fmaf_rn(x2, n,  4.89352455891786e-03f);
    n = __fmul_rn(xc, n);
    float d = __fmaf_rn(x2, 1.19825839466702e-06f, 1.18534705686654e-04f);
    d = __fmaf_rn(x2, d, 2.26843463243900e-03f);
    d = __fmaf_rn(x2, d, 4.89352518554385e-03f);
    return (fabsf(x) < 0.0004f) ? x : __fdiv_rn(n, d);
}

// ---------------- fast 128x128x8 SGEMM: C = op(A) @ B^T ----------------------
// Requirements: M%128==0, N%128==0, K%8==0 (true for all uses here).
// Bit-exact per-output: single accumulator, ascending-k __fmaf_rn chain.
template<bool GATHER>
__global__ __launch_bounds__(256)
void gemm128(const float* __restrict__ A, const float* __restrict__ B,
             const int* __restrict__ gidx, float* __restrict__ C,
             int M, int N, int K)
{
    __shared__ float As[8][128];
    __shared__ float Bs[8][128];

    const int tid = threadIdx.x;
    const int bm = blockIdx.y * 128;
    const int bn = blockIdx.x * 128;
    const int tx = tid & 15;
    const int ty = tid >> 4;
    const int lr = tid >> 1;            // loader row 0..127
    const int lk = (tid & 1) << 2;      // loader k offset 0 or 4

    size_t arow = (size_t)(bm + lr);
    if (GATHER) {
        int gi = gidx[bm + lr];
        if ((unsigned)gi >= (unsigned)VOCAB) gi = 0;
        arow = (size_t)gi;
    }
    const float* Ap = A + arow * (size_t)K + lk;
    const float* Bp = B + (size_t)(bn + lr) * K + lk;

    float acc[8][8];
    #pragma unroll
    for (int i = 0; i < 8; ++i)
        #pragma unroll
        for (int j = 0; j < 8; ++j) acc[i][j] = 0.f;

    float4 pa = *(const float4*)Ap;
    float4 pb = *(const float4*)Bp;

    for (int k0 = 8; k0 <= K; k0 += 8) {
        // stage current tile
        As[lk+0][lr] = pa.x; As[lk+1][lr] = pa.y;
        As[lk+2][lr] = pa.z; As[lk+3][lr] = pa.w;
        Bs[lk+0][lr] = pb.x; Bs[lk+1][lr] = pb.y;
        Bs[lk+2][lr] = pb.z; Bs[lk+3][lr] = pb.w;
        __syncthreads();

        if (k0 < K) {                    // prefetch next tile
            pa = *(const float4*)(Ap + k0);
            pb = *(const float4*)(Bp + k0);
        }

        #pragma unroll
        for (int k = 0; k < 8; ++k) {    // ascending k — bit-exact chains
            float4 a0 = *(const float4*)&As[k][ty << 2];
            float4 a1 = *(const float4*)&As[k][(ty << 2) + 64];
            float4 b0 = *(const float4*)&Bs[k][tx << 2];
            float4 b1 = *(const float4*)&Bs[k][(tx << 2) + 64];
            float av[8] = {a0.x,a0.y,a0.z,a0.w,a1.x,a1.y,a1.z,a1.w};
            float bv[8] = {b0.x,b0.y,b0.z,b0.w,b1.x,b1.y,b1.z,b1.w};
            #pragma unroll
            for (int i = 0; i < 8; ++i)
                #pragma unroll
                for (int j = 0; j < 8; ++j)
                    acc[i][j] = __fmaf_rn(av[i], bv[j], acc[i][j]);
        }
        __syncthreads();
    }

    #pragma unroll
    for (int i = 0; i < 8; ++i) {
        int gr = bm + (ty << 2) + (i & 3) + ((i >> 2) << 6);
        size_t ro = (size_t)gr * N;
        #pragma unroll
        for (int j = 0; j < 8; ++j) {
            int gc = bn + (tx << 2) + (j & 3) + ((j >> 2) << 6);
            C[ro + gc] = acc[i][j];
        }
    }
}

// ---------------- persistent scan kernel (validated in R13) ------------------
__device__ __forceinline__ void grid_barrier()
{
    __syncthreads();
    if (threadIdx.x == 0) {
        __threadfence();
        unsigned gen = g_bar_gen;
        if (atomicAdd(&g_bar_count, 1u) == NCTA - 1) {
            *(volatile unsigned*)&g_bar_count = 0;
            __threadfence();
            g_bar_gen = gen + 1;
        } else {
            while (g_bar_gen == gen) __nanosleep(32);
        }
        __threadfence();
    }
    __syncthreads();
}

__global__ __launch_bounds__(256, 1)
void scan_persistent(const float* __restrict__ Wh0, const float* __restrict__ Wh1,
                     const float* __restrict__ bh0)
{
    extern __shared__ float sm[];
    float* w0  = sm;              // [1024][8]  Wh0 slice, [k][c]
    float* wc  = sm + 8192;       // [1024][8]  Wc slice
    float* wh  = sm + 16384;      // [1024][8]  Wh1 slice
    float* As  = sm + 24576;      // [32][64]   h0 staging, [k][row]
    float* As2 = sm + 26624;      // [32][64]   h1 staging

    const int tid = threadIdx.x;
    const int bid = blockIdx.x;
    const int j0  = bid << 3;
    const int r   = tid >> 2;
    const int cg  = tid & 3;
    const int lc  = cg << 1;

    for (int i = tid; i < 8 * HID; i += 256) {
        int j = i >> 10;
        int k = i & 1023;
        w0[k*8 + j] = Wh0 [(size_t)(j0 + j) * HID + k];
        wc[k*8 + j] = g_Wc[(size_t)(j0 + j) * HID + k];
        wh[k*8 + j] = Wh1 [(size_t)(j0 + j) * HID + k];
    }
    float bh0c0 = bh0[j0 + lc], bh0c1 = bh0[j0 + lc + 1];
    float cb1c0 = g_cb1[j0 + lc], cb1c1 = g_cb1[j0 + lc + 1];

    const int lr = tid >> 2;
    const int lk = (tid & 3) << 2;

    grid_barrier();

    for (int t = 0; t < SEQ; ++t) {
        const float* h0_in = g_h0 + (size_t)(t & 1) * SB;
        const float* h1_in = g_H1 + (size_t)t * SB;
        const float* Xp_t  = g_Xp + (size_t)t * SB;
        float* h0_out = g_h0 + (size_t)((t + 1) & 1) * SB;
        float* h1_out = g_H1 + (size_t)(t + 1) * SB;

        float a00 = 0.f, a01 = 0.f;
        float c00 = 0.f, c01 = 0.f;
        float h00 = 0.f, h01 = 0.f;

        for (int kb = 0; kb < HID; kb += 32) {
            #pragma unroll
            for (int h = 0; h < 32; h += 16) {
                float4 v0 = __ldcg((const float4*)&h0_in[(size_t)lr * HID + kb + lk + h]);
                As[(lk+h+0)*64 + lr] = v0.x; As[(lk+h+1)*64 + lr] = v0.y;
                As[(lk+h+2)*64 + lr] = v0.z; As[(lk+h+3)*64 + lr] = v0.w;
                float4 v1 = __ldcg((const float4*)&h1_in[(size_t)lr * HID + kb + lk + h]);
                As2[(lk+h+0)*64 + lr] = v1.x; As2[(lk+h+1)*64 + lr] = v1.y;
                As2[(lk+h+2)*64 + lr] = v1.z; As2[(lk+h+3)*64 + lr] = v1.w;
            }
            __syncthreads();

            #pragma unroll
            for (int k = 0; k < 32; ++k) {
                float a0 = As [k*64 + r];
                float a1 = As2[k*64 + r];
                int cb = (kb + k) * 8 + lc;
                float2 W0 = *(const float2*)&w0[cb];
                float2 WC = *(const float2*)&wc[cb];
                float2 WH = *(const float2*)&wh[cb];
                a00 = __fmaf_rn(a0, W0.x, a00);  a01 = __fmaf_rn(a0, W0.y, a01);
                c00 = __fmaf_rn(a0, WC.x, c00);  c01 = __fmaf_rn(a0, WC.y, c01);
                h00 = __fmaf_rn(a1, WH.x, h00);  h01 = __fmaf_rn(a1, WH.y, h01);
            }
            __syncthreads();
        }

        {
            size_t o = (size_t)r * HID + j0 + lc;
            float v0 = __fadd_rn(__fadd_rn(Xp_t[o + 0], a00), bh0c0);
            float v1 = __fadd_rn(__fadd_rn(Xp_t[o + 1], a01), bh0c1);
            h0_out[o + 0] = xla_tanh(v0);
            h0_out[o + 1] = xla_tanh(v1);
            float u0 = __fadd_rn(__fadd_rn(c00, h00), cb1c0);
            float u1 = __fadd_rn(__fadd_rn(c01, h01), cb1c1);
            h1_out[o + 0] = xla_tanh(u0);
            h1_out[o + 1] = xla_tanh(u1);
        }

        grid_barrier();
    }
}

// ---------------- cp.async helper --------------------------------------------
__device__ __forceinline__ void cp16(uint32_t saddr, const void* gaddr)
{
    asm volatile("cp.async.cg.shared.global [%0], [%1], 16;" :: "r"(saddr), "l"(gaddr));
}

// ---------------- TF32 wmma logits, cp.async double-buffered -----------------
// dynamic smem: As[2][128][36] + Bs[2][128][36] floats = 73728 bytes.
// epilogue staging buffer aliased onto the same smem (after final wait+sync).
__global__ __launch_bounds__(256)
void logits_wmma(const float* __restrict__ H1all, const float* __restrict__ by1,
                 float* __restrict__ out)
{
    using namespace nvcuda;
    extern __shared__ float smd[];
    float* Asf = smd;                 // [2][128][36]
    float* Bsf = smd + 2*128*36;      // [2][128][36]

    const int tid  = threadIdx.x;
    const int wid  = tid >> 5;
    const int lane = tid & 31;
    const int bm = blockIdx.y * 128;
    const int bn = blockIdx.x * 128;
    const int wm = (wid >> 1) * 32;
    const int wn = (wid & 1) * 64;

    const int rr = tid >> 1;               // loader row 0..127
    const int hf = (tid & 1) << 4;         // 0 or 16 (k-half)
    const uint32_t sbase = (uint32_t)__cvta_generic_to_shared(smd);

    wmma::fragment<wmma::accumulator, 16, 16, 8, float> acc[2][4];
    #pragma unroll
    for (int mi = 0; mi < 2; ++mi)
        #pragma unroll
        for (int ni = 0; ni < 4; ++ni)
            wmma::fill_fragment(acc[mi][ni], 0.f);

    const int NT = HID / 32;   // 32 k-tiles

    // prologue: load stage 0
    {
        const float* ga = H1all + (size_t)(bm + rr) * HID + hf;
        const float* gb = g_Wy1p + (size_t)(bn + rr) * HID + hf;
        uint32_t sa = sbase + (uint32_t)(((0*128 + rr)*36 + hf) * 4);
        uint32_t sb = sbase + (uint32_t)((2*128*36 + (0*128 + rr)*36 + hf) * 4);
        cp16(sa,      ga);      cp16(sa + 16, ga + 4);
        cp16(sa + 32, ga + 8);  cp16(sa + 48, ga + 12);
        cp16(sb,      gb);      cp16(sb + 16, gb + 4);
        cp16(sb + 32, gb + 8);  cp16(sb + 48, gb + 12);
        asm volatile("cp.async.commit_group;");
    }

    for (int it = 0; it < NT; ++it) {
        if (it + 1 < NT) {
            int s = (it + 1) & 1;
            int k0 = (it + 1) * 32;
            const float* ga = H1all + (size_t)(bm + rr) * HID + k0 + hf;
            const float* gb = g_Wy1p + (size_t)(bn + rr) * HID + k0 + hf;
            uint32_t sa = sbase + (uint32_t)(((s*128 + rr)*36 + hf) * 4);
            uint32_t sb = sbase + (uint32_t)((2*128*36 + (s*128 + rr)*36 + hf) * 4);
            cp16(sa,      ga);      cp16(sa + 16, ga + 4);
            cp16(sa + 32, ga + 8);  cp16(sa + 48, ga + 12);
            cp16(sb,      gb);      cp16(sb + 16, gb + 4);
            cp16(sb + 32, gb + 8);  cp16(sb + 48, gb + 12);
            asm volatile("cp.async.commit_group;");
            asm volatile("cp.async.wait_group 1;");
        } else {
            asm volatile("cp.async.wait_group 0;");
        }
        __syncthreads();

        const int s = it & 1;
        const float* Ab = Asf + (size_t)s * 128 * 36;
        const float* Bb = Bsf + (size_t)s * 128 * 36;

        #pragma unroll
        for (int ks = 0; ks < 32; ks += 8) {
            wmma::fragment<wmma::matrix_a, 16, 16, 8, wmma::precision::tf32, wmma::row_major> af[2];
            wmma::fragment<wmma::matrix_b, 16, 16, 8, wmma::precision::tf32, wmma::col_major> bf[4];
            #pragma unroll
            for (int mi = 0; mi < 2; ++mi) {
                wmma::load_matrix_sync(af[mi], Ab + (size_t)(wm + mi*16)*36 + ks, 36);
                #pragma unroll
                for (int e = 0; e < af[mi].num_elements; ++e)
                    af[mi].x[e] = wmma::__float_to_tf32(af[mi].x[e]);
            }
            #pragma unroll
            for (int ni = 0; ni < 4; ++ni) {
                wmma::load_matrix_sync(bf[ni], Bb + (size_t)(wn + ni*16)*36 + ks, 36);
                #pragma unroll
                for (int e = 0; e < bf[ni].num_elements; ++e)
                    bf[ni].x[e] = wmma::__float_to_tf32(bf[ni].x[e]);
            }
            #pragma unroll
            for (int mi = 0; mi < 2; ++mi)
                #pragma unroll
                for (int ni = 0; ni < 4; ++ni)
                    wmma::mma_sync(acc[mi][ni], af[mi], bf[ni], acc[mi][ni]);
        }
        __syncthreads();
    }

    // epilogue: alias staging onto smem (all loads drained)
    float* st = smd + (size_t)wid * 320;    // 16x20 per warp
    #pragma unroll
    for (int mi = 0; mi < 2; ++mi)
        #pragma unroll
        for (int ni = 0; ni < 4; ++ni) {
            wmma::store_matrix_sync(st, acc[mi][ni], 20, wmma::mem_row_major);
            __syncwarp();
            #pragma unroll
            for (int e = 0; e < 8; ++e) {
                int idx = e * 32 + lane;
                int r2 = idx >> 4, c2 = idx & 15;
                int gr = bm + wm + mi*16 + r2;
                int gc = bn + wn + ni*16 + c2;
                if (gc < VOCAB)
                    out[(size_t)gr * VOCAB + gc] = __fadd_rn(st[r2*20 + c2], by1[gc]);
            }
            __syncwarp();
        }
}

// ---------------- small helper kernels ---------------------------------------
__global__ void pad_wy1_fix(const float* __restrict__ Wy1)
{
    size_t idx = (size_t)blockIdx.x * 256 + threadIdx.x;
    int n = (int)(idx >> 10);
    int k = (int)(idx & 1023);
    g_Wy1p[idx] = (n < VOCAB) ? Wy1[(size_t)n * HID + k] : 0.f;
}

__global__ void transpose_wy0(const float* __restrict__ Wy0)
{
    int idx = blockIdx.x * 256 + threadIdx.x;
    int j = idx >> 10, k = idx & 1023;
    g_Wy0T[(size_t)j * HID + k] = Wy0[(size_t)k * HID + j];
}

__global__ void cb1_kernel(const float* __restrict__ bh1, const float* __restrict__ by0,
                           const float* __restrict__ Wx1)
{
    int j = blockIdx.x;
    const float* row = Wx1 + (size_t)j * HID;
    float s = 0.f;
    for (int k = threadIdx.x; k < HID; k += 128) s += by0[k] * row[k];
    for (int off = 16; off > 0; off >>= 1) s += __shfl_xor_sync(0xffffffffu, s, off);
    __shared__ float ws[4];
    if ((threadIdx.x & 31) == 0) ws[threadIdx.x >> 5] = s;
    __syncthreads();
    if (threadIdx.x == 0) g_cb1[j] = ws[0] + ws[1] + ws[2] + ws[3] + bh1[j];
}

__global__ void prologue(const float* __restrict__ hidden,
                         float* __restrict__ h0b, float* __restrict__ h1b)
{
    int i = blockIdx.x * 256 + threadIdx.x;
    h0b[i] = hidden[i];
    h1b[i] = hidden[SB + i];
}

__global__ void tail(const float* __restrict__ h0f, const float* __restrict__ h1f,
                     float* __restrict__ out)
{
    int i = blockIdx.x * 256 + threadIdx.x;
    out[i]      = h0f[i];
    out[SB + i] = h1f[i];
}

// ---------------- launcher ---------------------------------------------------
extern "C" void kernel_launch(void* const* d_in, const int* in_sizes, int n_in,
                              void* d_out, int out_size)
{
    const int*   tok    = (const int*)  d_in[0];
    const float* hidden = (const float*)d_in[1];
    const float* emb    = (const float*)d_in[2];
    const float* Wx0    = (const float*)d_in[3];
    const float* Wh0    = (const float*)d_in[4];
    const float* bh0    = (const float*)d_in[5];
    const float* Wy0    = (const float*)d_in[6];
    const float* by0    = (const float*)d_in[7];
    const float* Wx1    = (const float*)d_in[8];
    const float* Wh1    = (const float*)d_in[9];
    const float* bh1    = (const float*)d_in[10];
    const float* Wy1    = (const float*)d_in[11];
    const float* by1    = (const float*)d_in[12];
    (void)in_sizes; (void)n_in;

    float *Xp, *H1, *h0, *WcP, *Wy0T;
    cudaGetSymbolAddress((void**)&Xp,   g_Xp);
    cudaGetSymbolAddress((void**)&H1,   g_H1);
    cudaGetSymbolAddress((void**)&h0,   g_h0);
    cudaGetSymbolAddress((void**)&WcP,  g_Wc);
    cudaGetSymbolAddress((void**)&Wy0T, g_Wy0T);

    const int SMEM_SCAN = (3 * 8 * HID + 2 * 32 * 64) * sizeof(float);  // 114688
    cudaFuncSetAttribute(scan_persistent,
                         cudaFuncAttributeMaxDynamicSharedMemorySize, SMEM_SCAN);
    const int SMEM_LOGITS = 2 * 2 * 128 * 36 * sizeof(float);           // 73728
    cudaFuncSetAttribute(logits_wmma,
                         cudaFuncAttributeMaxDynamicSharedMemorySize, SMEM_LOGITS);

    // 1) Xp = gather(emb, tok) @ Wx0^T   (raw, BIT-EXACT chain, fast tiles)
    gemm128<true><<<dim3(HID/128, TB/128), 256>>>(
        emb, Wx0, tok, Xp, TB, HID, HID);

    // 2) precompute (tolerant h1 path): Wy0T, Wc = Wx1 @ Wy0, cb1; pad Wy1
    transpose_wy0<<<HID*HID/256, 256>>>(Wy0);
    gemm128<false><<<dim3(HID/128, HID/128), 256>>>(
        Wx1, Wy0T, nullptr, WcP, HID, HID, HID);
    cb1_kernel<<<HID, 128>>>(bh1, by0, Wx1);
    pad_wy1_fix<<<(NPAD*HID)/256, 256>>>(Wy1);

    // 3) initial states
    prologue<<<SB/256, 256>>>(hidden, h0, H1);

    // 4) sequential scan — ONE persistent launch for all 128 steps
    scan_persistent<<<NCTA, 256, SMEM_SCAN>>>(Wh0, Wh1, bh0);

    // 5) logits = H1[0:128] @ Wy1^T + by1   (TF32 tensor cores, pipelined)
    logits_wmma<<<dim3(NPAD/128, TB/128), 256, SMEM_LOGITS>>>(H1, by1, (float*)d_out);

    // 6) final hidden states appended if out buffer includes them
    long total = (long)TB * VOCAB + 2L * SB;
    if ((long)out_size >= total)
        tail<<<SB/256, 256>>>(h0, H1 + (size_t)SEQ * SB,
                              (float*)d_out + (size_t)TB * VOCAB);
}

// round 15
// speedup vs baseline: 1.2502x; 1.2502x over previous
#include <cuda_runtime.h>
#include <mma.h>
#include <math.h>
#include <stdint.h>

#define SEQ   128
#define BATCH 64
#define HID   1024
#define VOCAB 10000
#define NPAD  10112              /* 79 * 128 */
#define TB    (SEQ*BATCH)        /* 8192 */
#define SB    (BATCH*HID)        /* 65536 */
#define NCTA  128                /* persistent scan grid (<= 148 SMs) */

// ---------------- device scratch (no allocations allowed) -------------------
__device__ float g_Xp[TB*HID];          // RAW x_t @ Wx0^T (no bias), all steps
__device__ float g_H1[(SEQ+1)*SB];      // slot t = h1 entering step t
__device__ float g_h0[2*SB];            // h0 ping-pong
__device__ float g_Wc[HID*HID];         // Wx1 @ Wy0
__device__ float g_Wy0T[HID*HID];       // Wy0 transposed
__device__ float g_Wy1p[NPAD*HID];      // zero-padded Wy1

// persistent-scan barrier state
__device__ unsigned g_bar_count;
__device__ volatile unsigned g_bar_gen;

// ---------------- XLA EmitFastTanh, FMA-contracted (verified passing) --------
__device__ __forceinline__ float xla_tanh(float x)
{
    const float kClamp = 7.90531110763549805f;
    float xc = fminf(fmaxf(x, -kClamp), kClamp);
    float x2 = __fmul_rn(xc, xc);
    float n = __fmaf_rn(x2, -2.76076847742355e-16f, 2.00018790482477e-13f);
    n = __fmaf_rn(x2, n, -8.60467152213735e-11f);
    n = __fmaf_rn(x2, n,  5.12229709037114e-08f);
    n = __fmaf_rn(x2, n,  1.48572235717979e-05f);
    n = __fmaf_rn(x2, n,  6.37261928875436e-04f);
    n = __fmaf_rn(x2, n,  4.89352455891786e-03f);
    n = __fmul_rn(xc, n);
    float d = __fmaf_rn(x2, 1.19825839466702e-06f, 1.18534705686654e-04f);
    d = __fmaf_rn(x2, d, 2.26843463243900e-03f);
    d = __fmaf_rn(x2, d, 4.89352518554385e-03f);
    return (fabsf(x) < 0.0004f) ? x : __fdiv_rn(n, d);
}

// ---------------- cp.async helper --------------------------------------------
__device__ __forceinline__ void cp16(uint32_t saddr, const void* gaddr)
{
    asm volatile("cp.async.cg.shared.global [%0], [%1], 16;" :: "r"(saddr), "l"(gaddr));
}

// ---------------- fast 128x128x8 SGEMM: C = op(A) @ B^T ----------------------
// Bit-exact per-output: single accumulator, ascending-k __fmaf_rn chain.
template<bool GATHER>
__global__ __launch_bounds__(256)
void gemm128(const float* __restrict__ A, const float* __restrict__ B,
             const int* __restrict__ gidx, float* __restrict__ C,
             int M, int N, int K)
{
    __shared__ float As[8][128];
    __shared__ float Bs[8][128];

    const int tid = threadIdx.x;
    const int bm = blockIdx.y * 128;
    const int bn = blockIdx.x * 128;
    const int tx = tid & 15;
    const int ty = tid >> 4;
    const int lr = tid >> 1;
    const int lk = (tid & 1) << 2;

    size_t arow = (size_t)(bm + lr);
    if (GATHER) {
        int gi = gidx[bm + lr];
        if ((unsigned)gi >= (unsigned)VOCAB) gi = 0;
        arow = (size_t)gi;
    }
    const float* Ap = A + arow * (size_t)K + lk;
    const float* Bp = B + (size_t)(bn + lr) * K + lk;

    float acc[8][8];
    #pragma unroll
    for (int i = 0; i < 8; ++i)
        #pragma unroll
        for (int j = 0; j < 8; ++j) acc[i][j] = 0.f;

    float4 pa = *(const float4*)Ap;
    float4 pb = *(const float4*)Bp;

    for (int k0 = 8; k0 <= K; k0 += 8) {
        As[lk+0][lr] = pa.x; As[lk+1][lr] = pa.y;
        As[lk+2][lr] = pa.z; As[lk+3][lr] = pa.w;
        Bs[lk+0][lr] = pb.x; Bs[lk+1][lr] = pb.y;
        Bs[lk+2][lr] = pb.z; Bs[lk+3][lr] = pb.w;
        __syncthreads();

        if (k0 < K) {
            pa = *(const float4*)(Ap + k0);
            pb = *(const float4*)(Bp + k0);
        }

        #pragma unroll
        for (int k = 0; k < 8; ++k) {
            float4 a0 = *(const float4*)&As[k][ty << 2];
            float4 a1 = *(const float4*)&As[k][(ty << 2) + 64];
            float4 b0 = *(const float4*)&Bs[k][tx << 2];
            float4 b1 = *(const float4*)&Bs[k][(tx << 2) + 64];
            float av[8] = {a0.x,a0.y,a0.z,a0.w,a1.x,a1.y,a1.z,a1.w};
            float bv[8] = {b0.x,b0.y,b0.z,b0.w,b1.x,b1.y,b1.z,b1.w};
            #pragma unroll
            for (int i = 0; i < 8; ++i)
                #pragma unroll
                for (int j = 0; j < 8; ++j)
                    acc[i][j] = __fmaf_rn(av[i], bv[j], acc[i][j]);
        }
        __syncthreads();
    }

    #pragma unroll
    for (int i = 0; i < 8; ++i) {
        int gr = bm + (ty << 2) + (i & 3) + ((i >> 2) << 6);
        size_t ro = (size_t)gr * N;
        #pragma unroll
        for (int j = 0; j < 8; ++j) {
            int gc = bn + (tx << 2) + (j & 3) + ((j >> 2) << 6);
            C[ro + gc] = acc[i][j];
        }
    }
}

// ---------------- persistent scan kernel -------------------------------------
// smem layout (floats):
//   w0   [0      .. 8192)   Wh0 slice  [k][8]
//   wc   [8192   .. 16384)  Wc  slice  [k][8]
//   wh   [16384  .. 24576)  Wh1 slice  [k][8]
//   stA  [24576  .. 29184)  h0 staging 2 x [64][36]
//   stB  [29184  .. 33792)  h1 staging 2 x [64][36]
//   cb1s [33792  .. 33800)
#define ST_TILE 2304   /* 64*36 */

__device__ __forceinline__ void grid_barrier()
{
    __syncthreads();
    if (threadIdx.x == 0) {
        __threadfence();
        unsigned gen = g_bar_gen;
        if (atomicAdd(&g_bar_count, 1u) == NCTA - 1) {
            *(volatile unsigned*)&g_bar_count = 0;
            __threadfence();
            g_bar_gen = gen + 1;
        } else {
            while (g_bar_gen == gen) __nanosleep(32);
        }
        __threadfence();
    }
    __syncthreads();
}

__global__ __launch_bounds__(256, 1)
void scan_persistent(const float* __restrict__ Wh0, const float* __restrict__ Wh1,
                     const float* __restrict__ bh0,
                     const float* __restrict__ Wx1, const float* __restrict__ bh1,
                     const float* __restrict__ by0,
                     const float* __restrict__ hidden)
{
    extern __shared__ float sm[];
    float* w0   = sm;
    float* wc   = sm + 8192;
    float* wh   = sm + 16384;
    float* stA  = sm + 24576;
    float* stB  = sm + 29184;
    float* cb1s = sm + 33792;

    const int tid = threadIdx.x;
    const int bid = blockIdx.x;
    const int j0  = bid << 3;
    const int r   = tid >> 2;          // output row 0..63
    const int lc  = (tid & 3) << 1;    // local col 0,2,4,6

    // ---- init phase: weights, initial state copy, cb1 ----
    for (int i = tid; i < 8 * HID; i += 256) {
        int j = i >> 10;
        int k = i & 1023;
        w0[k*8 + j] = Wh0 [(size_t)(j0 + j) * HID + k];
        wc[k*8 + j] = g_Wc[(size_t)(j0 + j) * HID + k];
        wh[k*8 + j] = Wh1 [(size_t)(j0 + j) * HID + k];
    }
    // initial states: this CTA copies its 512-element chunks
    {
        int base = bid * 512;
        for (int i = tid; i < 512; i += 256) {
            g_h0[base + i] = hidden[base + i];
            g_H1[base + i] = hidden[SB + base + i];
        }
    }
    // cb1 for local cols: warp w -> col j0+w   (h1-tolerant path)
    {
        int w = tid >> 5, lane = tid & 31;
        const float* row = Wx1 + (size_t)(j0 + w) * HID;
        float s = 0.f;
        for (int k = lane; k < HID; k += 32)
            s = __fmaf_rn(by0[k], row[k], s);
        #pragma unroll
        for (int o = 16; o > 0; o >>= 1) s += __shfl_xor_sync(0xffffffffu, s, o);
        if (lane == 0) cb1s[w] = __fadd_rn(s, bh1[j0 + w]);
    }
    float bh0c0 = bh0[j0 + lc], bh0c1 = bh0[j0 + lc + 1];

    const uint32_t sbase = (uint32_t)__cvta_generic_to_shared(sm);
    const uint32_t stA_b = sbase + 24576u * 4u;
    const uint32_t stB_b = sbase + 29184u * 4u;

    // loader mapping: thread covers rows lrow, k-offsets lkq and lkq+4
    const int lrow = tid >> 2;             // 0..63
    const int lkq  = (tid & 3) << 3;       // 0,8,16,24

    grid_barrier();   // weights loaded everywhere; init state visible
    float cb1c0 = cb1s[lc], cb1c1 = cb1s[lc + 1];

    for (int t = 0; t < SEQ; ++t) {
        const float* h0_in = g_h0 + (size_t)(t & 1) * SB;
        const float* h1_in = g_H1 + (size_t)t * SB;
        const float* Xp_t  = g_Xp + (size_t)t * SB;
        float* h0_out = g_h0 + (size_t)((t + 1) & 1) * SB;
        float* h1_out = g_H1 + (size_t)(t + 1) * SB;

        float a00 = 0.f, a01 = 0.f;
        float c00 = 0.f, c01 = 0.f;
        float h00 = 0.f, h01 = 0.f;

        // prologue: stage tile 0
        {
            const float* g0 = h0_in + (size_t)lrow * HID + lkq;
            const float* g1 = h1_in + (size_t)lrow * HID + lkq;
            uint32_t dA = stA_b + (uint32_t)((lrow * 36 + lkq) * 4);
            uint32_t dB = stB_b + (uint32_t)((lrow * 36 + lkq) * 4);
            cp16(dA, g0); cp16(dA + 16, g0 + 4);
            cp16(dB, g1); cp16(dB + 16, g1 + 4);
            asm volatile("cp.async.commit_group;");
        }

        for (int kt = 0; kt < 32; ++kt) {
            if (kt + 1 < 32) {
                int s = (kt + 1) & 1;
                int kb = (kt + 1) << 5;
                const float* g0 = h0_in + (size_t)lrow * HID + kb + lkq;
                const float* g1 = h1_in + (size_t)lrow * HID + kb + lkq;
                uint32_t dA = stA_b + (uint32_t)((s * ST_TILE + lrow * 36 + lkq) * 4);
                uint32_t dB = stB_b + (uint32_t)((s * ST_TILE + lrow * 36 + lkq) * 4);
                cp16(dA, g0); cp16(dA + 16, g0 + 4);
                cp16(dB, g1); cp16(dB + 16, g1 + 4);
                asm volatile("cp.async.commit_group;");
                asm volatile("cp.async.wait_group 1;");
            } else {
                asm volatile("cp.async.wait_group 0;");
            }
            __syncthreads();

            const int s = kt & 1;
            const float* A0 = stA + s * ST_TILE + r * 36;
            const float* A1 = stB + s * ST_TILE + r * 36;
            const int kb = kt << 5;

            #pragma unroll
            for (int k = 0; k < 32; ++k) {   // ascending k — bit-exact chains
                float a0 = A0[k];
                float a1 = A1[k];
                int cb = (kb + k) * 8 + lc;
                float2 W0 = *(const float2*)&w0[cb];
                float2 WC = *(const float2*)&wc[cb];
                float2 WH = *(const float2*)&wh[cb];
                a00 = __fmaf_rn(a0, W0.x, a00);  a01 = __fmaf_rn(a0, W0.y, a01);
                c00 = __fmaf_rn(a0, WC.x, c00);  c01 = __fmaf_rn(a0, WC.y, c01);
                h00 = __fmaf_rn(a1, WH.x, h00);  h01 = __fmaf_rn(a1, WH.y, h01);
            }
            __syncthreads();
        }

        // epilogues (identical arithmetic to validated version)
        {
            size_t o = (size_t)r * HID + j0 + lc;
            float v0 = __fadd_rn(__fadd_rn(Xp_t[o + 0], a00), bh0c0);
            float v1 = __fadd_rn(__fadd_rn(Xp_t[o + 1], a01), bh0c1);
            h0_out[o + 0] = xla_tanh(v0);
            h0_out[o + 1] = xla_tanh(v1);
            float u0 = __fadd_rn(__fadd_rn(c00, h00), cb1c0);
            float u1 = __fadd_rn(__fadd_rn(c01, h01), cb1c1);
            h1_out[o + 0] = xla_tanh(u0);
            h1_out[o + 1] = xla_tanh(u1);
        }

        grid_barrier();
    }
}

// ---------------- TF32 wmma logits, cp.async double-buffered -----------------
__global__ __launch_bounds__(256)
void logits_wmma(const float* __restrict__ H1all, const float* __restrict__ by1,
                 float* __restrict__ out)
{
    using namespace nvcuda;
    extern __shared__ float smd[];
    float* Asf = smd;                 // [2][128][36]
    float* Bsf = smd + 2*128*36;      // [2][128][36]

    const int tid  = threadIdx.x;
    const int wid  = tid >> 5;
    const int lane = tid & 31;
    const int bm = blockIdx.y * 128;
    const int bn = blockIdx.x * 128;
    const int wm = (wid >> 1) * 32;
    const int wn = (wid & 1) * 64;

    const int rr = tid >> 1;
    const int hf = (tid & 1) << 4;
    const uint32_t sbase = (uint32_t)__cvta_generic_to_shared(smd);

    wmma::fragment<wmma::accumulator, 16, 16, 8, float> acc[2][4];
    #pragma unroll
    for (int mi = 0; mi < 2; ++mi)
        #pragma unroll
        for (int ni = 0; ni < 4; ++ni)
            wmma::fill_fragment(acc[mi][ni], 0.f);

    const int NT = HID / 32;

    {
        const float* ga = H1all + (size_t)(bm + rr) * HID + hf;
        const float* gb = g_Wy1p + (size_t)(bn + rr) * HID + hf;
        uint32_t sa = sbase + (uint32_t)(((0*128 + rr)*36 + hf) * 4);
        uint32_t sb = sbase + (uint32_t)((2*128*36 + (0*128 + rr)*36 + hf) * 4);
        cp16(sa,      ga);      cp16(sa + 16, ga + 4);
        cp16(sa + 32, ga + 8);  cp16(sa + 48, ga + 12);
        cp16(sb,      gb);      cp16(sb + 16, gb + 4);
        cp16(sb + 32, gb + 8);  cp16(sb + 48, gb + 12);
        asm volatile("cp.async.commit_group;");
    }

    for (int it = 0; it < NT; ++it) {
        if (it + 1 < NT) {
            int s = (it + 1) & 1;
            int k0 = (it + 1) * 32;
            const float* ga = H1all + (size_t)(bm + rr) * HID + k0 + hf;
            const float* gb = g_Wy1p + (size_t)(bn + rr) * HID + k0 + hf;
            uint32_t sa = sbase + (uint32_t)(((s*128 + rr)*36 + hf) * 4);
            uint32_t sb = sbase + (uint32_t)((2*128*36 + (s*128 + rr)*36 + hf) * 4);
            cp16(sa,      ga);      cp16(sa + 16, ga + 4);
            cp16(sa + 32, ga + 8);  cp16(sa + 48, ga + 12);
            cp16(sb,      gb);      cp16(sb + 16, gb + 4);
            cp16(sb + 32, gb + 8);  cp16(sb + 48, gb + 12);
            asm volatile("cp.async.commit_group;");
            asm volatile("cp.async.wait_group 1;");
        } else {
            asm volatile("cp.async.wait_group 0;");
        }
        __syncthreads();

        const int s = it & 1;
        const float* Ab = Asf + (size_t)s * 128 * 36;
        const float* Bb = Bsf + (size_t)s * 128 * 36;

        #pragma unroll
        for (int ks = 0; ks < 32; ks += 8) {
            wmma::fragment<wmma::matrix_a, 16, 16, 8, wmma::precision::tf32, wmma::row_major> af[2];
            wmma::fragment<wmma::matrix_b, 16, 16, 8, wmma::precision::tf32, wmma::col_major> bf[4];
            #pragma unroll
            for (int mi = 0; mi < 2; ++mi) {
                wmma::load_matrix_sync(af[mi], Ab + (size_t)(wm + mi*16)*36 + ks, 36);
                #pragma unroll
                for (int e = 0; e < af[mi].num_elements; ++e)
                    af[mi].x[e] = wmma::__float_to_tf32(af[mi].x[e]);
            }
            #pragma unroll
            for (int ni = 0; ni < 4; ++ni) {
                wmma::load_matrix_sync(bf[ni], Bb + (size_t)(wn + ni*16)*36 + ks, 36);
                #pragma unroll
                for (int e = 0; e < bf[ni].num_elements; ++e)
                    bf[ni].x[e] = wmma::__float_to_tf32(bf[ni].x[e]);
            }
            #pragma unroll
            for (int mi = 0; mi < 2; ++mi)
                #pragma unroll
                for (int ni = 0; ni < 4; ++ni)
                    wmma::mma_sync(acc[mi][ni], af[mi], bf[ni], acc[mi][ni]);
        }
        __syncthreads();
    }

    float* st = smd + (size_t)wid * 320;
    #pragma unroll
    for (int mi = 0; mi < 2; ++mi)
        #pragma unroll
        for (int ni = 0; ni < 4; ++ni) {
            wmma::store_matrix_sync(st, acc[mi][ni], 20, wmma::mem_row_major);
            __syncwarp();
            #pragma unroll
            for (int e = 0; e < 8; ++e) {
                int idx = e * 32 + lane;
                int r2 = idx >> 4, c2 = idx & 15;
                int gr = bm + wm + mi*16 + r2;
                int gc = bn + wn + ni*16 + c2;
                if (gc < VOCAB)
                    out[(size_t)gr * VOCAB + gc] = __fadd_rn(st[r2*20 + c2], by1[gc]);
            }
            __syncwarp();
        }
}

// ---------------- small helper kernels ---------------------------------------
__global__ void pad_wy1_fix(const float* __restrict__ Wy1)
{
    size_t idx = (size_t)blockIdx.x * 256 + threadIdx.x;
    int n = (int)(idx >> 10);
    int k = (int)(idx & 1023);
    g_Wy1p[idx] = (n < VOCAB) ? Wy1[(size_t)n * HID + k] : 0.f;
}

__global__ void transpose_wy0(const float* __restrict__ Wy0)
{
    int idx = blockIdx.x * 256 + threadIdx.x;
    int j = idx >> 10, k = idx & 1023;
    g_Wy0T[(size_t)j * HID + k] = Wy0[(size_t)k * HID + j];
}

__global__ void tail(const float* __restrict__ h0f, const float* __restrict__ h1f,
                     float* __restrict__ out)
{
    int i = blockIdx.x * 256 + threadIdx.x;
    out[i]      = h0f[i];
    out[SB + i] = h1f[i];
}

// ---------------- launcher ---------------------------------------------------
extern "C" void kernel_launch(void* const* d_in, const int* in_sizes, int n_in,
                              void* d_out, int out_size)
{
    const int*   tok    = (const int*)  d_in[0];
    const float* hidden = (const float*)d_in[1];
    const float* emb    = (const float*)d_in[2];
    const float* Wx0    = (const float*)d_in[3];
    const float* Wh0    = (const float*)d_in[4];
    const float* bh0    = (const float*)d_in[5];
    const float* Wy0    = (const float*)d_in[6];
    const float* by0    = (const float*)d_in[7];
    const float* Wx1    = (const float*)d_in[8];
    const float* Wh1    = (const float*)d_in[9];
    const float* bh1    = (const float*)d_in[10];
    const float* Wy1    = (const float*)d_in[11];
    const float* by1    = (const float*)d_in[12];
    (void)in_sizes; (void)n_in;

    float *Xp, *H1, *h0, *WcP, *Wy0T;
    cudaGetSymbolAddress((void**)&Xp,   g_Xp);
    cudaGetSymbolAddress((void**)&H1,   g_H1);
    cudaGetSymbolAddress((void**)&h0,   g_h0);
    cudaGetSymbolAddress((void**)&WcP,  g_Wc);
    cudaGetSymbolAddress((void**)&Wy0T, g_Wy0T);

    const int SMEM_SCAN = 33800 * sizeof(float);               // 135200 B
    cudaFuncSetAttribute(scan_persistent,
                         cudaFuncAttributeMaxDynamicSharedMemorySize, SMEM_SCAN);
    const int SMEM_LOGITS = 2 * 2 * 128 * 36 * sizeof(float);  // 73728 B
    cudaFuncSetAttribute(logits_wmma,
                         cudaFuncAttributeMaxDynamicSharedMemorySize, SMEM_LOGITS);

    // (1) Xp = gather(emb, tok) @ Wx0^T   (raw, BIT-EXACT chain)
    gemm128<true><<<dim3(HID/128, TB/128), 256>>>(
        emb, Wx0, tok, Xp, TB, HID, HID);

    // (2) Wy0T ; (3) Wc = Wx1 @ Wy0   (tolerant h1 path)
    transpose_wy0<<<HID*HID/256, 256>>>(Wy0);
    gemm128<false><<<dim3(HID/128, HID/128), 256>>>(
        Wx1, Wy0T, nullptr, WcP, HID, HID, HID);

    // (4) persistent scan — fused init (state copy + cb1), all 128 steps
    scan_persistent<<<NCTA, 256, SMEM_SCAN>>>(Wh0, Wh1, bh0, Wx1, bh1, by0, hidden);

    // (5) pad Wy1 ; (6) logits = H1 @ Wy1^T + by1 (TF32 tensor cores)
    pad_wy1_fix<<<(NPAD*HID)/256, 256>>>(Wy1);
    logits_wmma<<<dim3(NPAD/128, TB/128), 256, SMEM_LOGITS>>>(H1, by1, (float*)d_out);

    // (7) final hidden states appended if out buffer includes them
    long total = (long)TB * VOCAB + 2L * SB;
    if ((long)out_size >= total)
        tail<<<SB/256, 256>>>(h0, H1 + (size_t)SEQ * SB,
                              (float*)d_out + (size_t)TB * VOCAB);
}

// round 16
// speedup vs baseline: 1.2947x; 1.0356x over previous
#include <cuda_runtime.h>
#include <mma.h>
#include <math.h>
#include <stdint.h>

#define SEQ   128
#define BATCH 64
#define HID   1024
#define VOCAB 10000
#define NPAD  10112              /* 79 * 128 */
#define TB    (SEQ*BATCH)        /* 8192 */
#define SB    (BATCH*HID)        /* 65536 */
#define NCTA  128                /* persistent scan grid (<= 148 SMs) */

// ---------------- device scratch (no allocations allowed) -------------------
__device__ float g_Xp[TB*HID];          // RAW x_t @ Wx0^T (no bias), all steps
__device__ float g_H1[(SEQ+1)*SB];      // slot t = h1 entering step t
__device__ float g_h0[2*SB];            // h0 ping-pong
__device__ float g_Wc[HID*HID];         // Wx1 @ Wy0
__device__ float g_Wy0T[HID*HID];       // Wy0 transposed
__device__ float g_Wy1p[NPAD*HID];      // zero-padded Wy1

// persistent-scan barrier state
__device__ unsigned g_bar_count;
__device__ volatile unsigned g_bar_gen;

// ---------------- XLA EmitFastTanh, FMA-contracted (verified passing) --------
__device__ __forceinline__ float xla_tanh(float x)
{
    const float kClamp = 7.90531110763549805f;
    float xc = fminf(fmaxf(x, -kClamp), kClamp);
    float x2 = __fmul_rn(xc, xc);
    float n = __fmaf_rn(x2, -2.76076847742355e-16f, 2.00018790482477e-13f);
    n = __fmaf_rn(x2, n, -8.60467152213735e-11f);
    n = __fmaf_rn(x2, n,  5.12229709037114e-08f);
    n = __fmaf_rn(x2, n,  1.48572235717979e-05f);
    n = __fmaf_rn(x2, n,  6.37261928875436e-04f);
    n = __fmaf_rn(x2, n,  4.89352455891786e-03f);
    n = __fmul_rn(xc, n);
    float d = __fmaf_rn(x2, 1.19825839466702e-06f, 1.18534705686654e-04f);
    d = __fmaf_rn(x2, d, 2.26843463243900e-03f);
    d = __fmaf_rn(x2, d, 4.89352518554385e-03f);
    return (fabsf(x) < 0.0004f) ? x : __fdiv_rn(n, d);
}

// ---------------- cp.async helper --------------------------------------------
__device__ __forceinline__ void cp16(uint32_t saddr, const void* gaddr)
{
    asm volatile("cp.async.cg.shared.global [%0], [%1], 16;" :: "r"(saddr), "l"(gaddr));
}

// ---------------- fast 128x128x8 SGEMM: C = op(A) @ B^T ----------------------
// Bit-exact per-output: single accumulator, ascending-k __fmaf_rn chain.
template<bool GATHER>
__global__ __launch_bounds__(256)
void gemm128(const float* __restrict__ A, const float* __restrict__ B,
             const int* __restrict__ gidx, float* __restrict__ C,
             int M, int N, int K)
{
    __shared__ float As[8][128];
    __shared__ float Bs[8][128];

    const int tid = threadIdx.x;
    const int bm = blockIdx.y * 128;
    const int bn = blockIdx.x * 128;
    const int tx = tid & 15;
    const int ty = tid >> 4;
    const int lr = tid >> 1;
    const int lk = (tid & 1) << 2;

    size_t arow = (size_t)(bm + lr);
    if (GATHER) {
        int gi = gidx[bm + lr];
        if ((unsigned)gi >= (unsigned)VOCAB) gi = 0;
        arow = (size_t)gi;
    }
    const float* Ap = A + arow * (size_t)K + lk;
    const float* Bp = B + (size_t)(bn + lr) * K + lk;

    float acc[8][8];
    #pragma unroll
    for (int i = 0; i < 8; ++i)
        #pragma unroll
        for (int j = 0; j < 8; ++j) acc[i][j] = 0.f;

    float4 pa = *(const float4*)Ap;
    float4 pb = *(const float4*)Bp;

    for (int k0 = 8; k0 <= K; k0 += 8) {
        As[lk+0][lr] = pa.x; As[lk+1][lr] = pa.y;
        As[lk+2][lr] = pa.z; As[lk+3][lr] = pa.w;
        Bs[lk+0][lr] = pb.x; Bs[lk+1][lr] = pb.y;
        Bs[lk+2][lr] = pb.z; Bs[lk+3][lr] = pb.w;
        __syncthreads();

        if (k0 < K) {
            pa = *(const float4*)(Ap + k0);
            pb = *(const float4*)(Bp + k0);
        }

        #pragma unroll
        for (int k = 0; k < 8; ++k) {
            float4 a0 = *(const float4*)&As[k][ty << 2];
            float4 a1 = *(const float4*)&As[k][(ty << 2) + 64];
            float4 b0 = *(const float4*)&Bs[k][tx << 2];
            float4 b1 = *(const float4*)&Bs[k][(tx << 2) + 64];
            float av[8] = {a0.x,a0.y,a0.z,a0.w,a1.x,a1.y,a1.z,a1.w};
            float bv[8] = {b0.x,b0.y,b0.z,b0.w,b1.x,b1.y,b1.z,b1.w};
            #pragma unroll
            for (int i = 0; i < 8; ++i)
                #pragma unroll
                for (int j = 0; j < 8; ++j)
                    acc[i][j] = __fmaf_rn(av[i], bv[j], acc[i][j]);
        }
        __syncthreads();
    }

    #pragma unroll
    for (int i = 0; i < 8; ++i) {
        int gr = bm + (ty << 2) + (i & 3) + ((i >> 2) << 6);
        size_t ro = (size_t)gr * N;
        #pragma unroll
        for (int j = 0; j < 8; ++j) {
            int gc = bn + (tx << 2) + (j & 3) + ((j >> 2) << 6);
            C[ro + gc] = acc[i][j];
        }
    }
}

// ---------------- persistent scan kernel -------------------------------------
// smem layout (floats):
//   w0   [0      .. 8192)    Wh0 slice, k-PAIRED: [kk][cg][{c0k0,c0k1,c1k0,c1k1}]
//   wc   [8192   .. 16384)   Wc  slice, paired
//   wh   [16384  .. 24576)   Wh1 slice, paired
//   stA  [24576  .. 31488)   h0 staging 3 x [64][36]
//   stB  [31488  .. 38400)   h1 staging 3 x [64][36]
//   cb1s [38400  .. 38408)
#define ST_TILE 2304   /* 64*36 */

__device__ __forceinline__ void grid_barrier()
{
    __syncthreads();
    if (threadIdx.x == 0) {
        __threadfence();
        unsigned gen = g_bar_gen;
        if (atomicAdd(&g_bar_count, 1u) == NCTA - 1) {
            *(volatile unsigned*)&g_bar_count = 0;
            __threadfence();
            g_bar_gen = gen + 1;
        } else {
            while (g_bar_gen == gen) __nanosleep(32);
        }
        __threadfence();
    }
    __syncthreads();
}

__global__ __launch_bounds__(256, 1)
void scan_persistent(const float* __restrict__ Wh0, const float* __restrict__ Wh1,
                     const float* __restrict__ bh0,
                     const float* __restrict__ Wx1, const float* __restrict__ bh1,
                     const float* __restrict__ by0,
                     const float* __restrict__ hidden)
{
    extern __shared__ float sm[];
    float* w0   = sm;
    float* wc   = sm + 8192;
    float* wh   = sm + 16384;
    float* stA  = sm + 24576;
    float* stB  = sm + 31488;
    float* cb1s = sm + 38400;

    const int tid = threadIdx.x;
    const int bid = blockIdx.x;
    const int j0  = bid << 3;
    const int r   = tid >> 2;          // output row 0..63
    const int cg  = tid & 3;           // col-pair index
    const int lc  = cg << 1;           // local col 0,2,4,6

    // ---- init: weights (k-paired layout), initial state copy, cb1 ----
    for (int i = tid; i < 8 * HID; i += 256) {
        int j = i >> 10;               // 0..7
        int k = i & 1023;
        int dst = (k >> 1) * 16 + (j >> 1) * 4 + ((j & 1) << 1) + (k & 1);
        w0[dst] = Wh0 [(size_t)(j0 + j) * HID + k];
        wc[dst] = g_Wc[(size_t)(j0 + j) * HID + k];
        wh[dst] = Wh1 [(size_t)(j0 + j) * HID + k];
    }
    {
        int base = bid * 512;
        for (int i = tid; i < 512; i += 256) {
            g_h0[base + i] = hidden[base + i];
            g_H1[base + i] = hidden[SB + base + i];
        }
    }
    {
        int w = tid >> 5, lane = tid & 31;
        const float* row = Wx1 + (size_t)(j0 + w) * HID;
        float s = 0.f;
        for (int k = lane; k < HID; k += 32)
            s = __fmaf_rn(by0[k], row[k], s);
        #pragma unroll
        for (int o = 16; o > 0; o >>= 1) s += __shfl_xor_sync(0xffffffffu, s, o);
        if (lane == 0) cb1s[w] = __fadd_rn(s, bh1[j0 + w]);
    }
    float bh0c0 = bh0[j0 + lc], bh0c1 = bh0[j0 + lc + 1];

    const uint32_t sbase = (uint32_t)__cvta_generic_to_shared(sm);
    const uint32_t stA_b = sbase + 24576u * 4u;
    const uint32_t stB_b = sbase + 31488u * 4u;

    const int lrow = tid >> 2;             // staging row 0..63
    const int lkq  = (tid & 3) << 3;       // staging k offset 0,8,16,24

    grid_barrier();
    float cb1c0 = cb1s[lc], cb1c1 = cb1s[lc + 1];

    for (int t = 0; t < SEQ; ++t) {
        const float* h0_in = g_h0 + (size_t)(t & 1) * SB;
        const float* h1_in = g_H1 + (size_t)t * SB;
        const float* Xp_t  = g_Xp + (size_t)t * SB;
        float* h0_out = g_h0 + (size_t)((t + 1) & 1) * SB;
        float* h1_out = g_H1 + (size_t)(t + 1) * SB;

        // prefetch the epilogue Xp operands early (hidden under k-loop)
        size_t oxy = (size_t)r * HID + j0 + lc;
        float2 xp2 = __ldcg((const float2*)&Xp_t[oxy]);

        float a00 = 0.f, a01 = 0.f;
        float c00 = 0.f, c01 = 0.f;
        float h00 = 0.f, h01 = 0.f;

        // prologue: stage tiles 0 and 1 (buffers 0, 1)
        #pragma unroll
        for (int p = 0; p < 2; ++p) {
            const float* g0 = h0_in + (size_t)lrow * HID + (p << 5) + lkq;
            const float* g1 = h1_in + (size_t)lrow * HID + (p << 5) + lkq;
            uint32_t dA = stA_b + (uint32_t)((p * ST_TILE + lrow * 36 + lkq) * 4);
            uint32_t dB = stB_b + (uint32_t)((p * ST_TILE + lrow * 36 + lkq) * 4);
            cp16(dA, g0); cp16(dA + 16, g0 + 4);
            cp16(dB, g1); cp16(dB + 16, g1 + 4);
            asm volatile("cp.async.commit_group;");
        }

        for (int kt = 0; kt < 32; ++kt) {
            if (kt < 31) { asm volatile("cp.async.wait_group 1;"); }
            else         { asm volatile("cp.async.wait_group 0;"); }
            __syncthreads();

            if (kt + 2 < 32) {          // stage tile kt+2 (buffer freed at sync)
                int b2 = (kt + 2) % 3;
                int kb2 = (kt + 2) << 5;
                const float* g0 = h0_in + (size_t)lrow * HID + kb2 + lkq;
                const float* g1 = h1_in + (size_t)lrow * HID + kb2 + lkq;
                uint32_t dA = stA_b + (uint32_t)((b2 * ST_TILE + lrow * 36 + lkq) * 4);
                uint32_t dB = stB_b + (uint32_t)((b2 * ST_TILE + lrow * 36 + lkq) * 4);
                cp16(dA, g0); cp16(dA + 16, g0 + 4);
                cp16(dB, g1); cp16(dB + 16, g1 + 4);
                asm volatile("cp.async.commit_group;");
            }

            const int b = kt % 3;
            const float* A0 = stA + b * ST_TILE + r * 36;
            const float* A1 = stB + b * ST_TILE + r * 36;
            const int kkb = (kt << 5) >> 1;     // k-pair base for this tile

            #pragma unroll
            for (int kq = 0; kq < 8; ++kq) {    // 4 k's per kq, ascending
                float4 av0 = *(const float4*)&A0[kq << 2];
                float4 av1 = *(const float4*)&A1[kq << 2];
                int wb0 = (kkb + (kq << 1)) * 16 + (cg << 2);
                int wb1 = wb0 + 16;
                float4 W0a = *(const float4*)&w0[wb0];
                float4 WCa = *(const float4*)&wc[wb0];
                float4 WHa = *(const float4*)&wh[wb0];
                // k, k+1  (ascending within each accumulator)
                a00 = __fmaf_rn(av0.x, W0a.x, a00); a00 = __fmaf_rn(av0.y, W0a.y, a00);
                a01 = __fmaf_rn(av0.x, W0a.z, a01); a01 = __fmaf_rn(av0.y, W0a.w, a01);
                c00 = __fmaf_rn(av0.x, WCa.x, c00); c00 = __fmaf_rn(av0.y, WCa.y, c00);
                c01 = __fmaf_rn(av0.x, WCa.z, c01); c01 = __fmaf_rn(av0.y, WCa.w, c01);
                h00 = __fmaf_rn(av1.x, WHa.x, h00); h00 = __fmaf_rn(av1.y, WHa.y, h00);
                h01 = __fmaf_rn(av1.x, WHa.z, h01); h01 = __fmaf_rn(av1.y, WHa.w, h01);
                float4 W0b = *(const float4*)&w0[wb1];
                float4 WCb = *(const float4*)&wc[wb1];
                float4 WHb = *(const float4*)&wh[wb1];
                // k+2, k+3
                a00 = __fmaf_rn(av0.z, W0b.x, a00); a00 = __fmaf_rn(av0.w, W0b.y, a00);
                a01 = __fmaf_rn(av0.z, W0b.z, a01); a01 = __fmaf_rn(av0.w, W0b.w, a01);
                c00 = __fmaf_rn(av0.z, WCb.x, c00); c00 = __fmaf_rn(av0.w, WCb.y, c00);
                c01 = __fmaf_rn(av0.z, WCb.z, c01); c01 = __fmaf_rn(av0.w, WCb.w, c01);
                h00 = __fmaf_rn(av1.z, WHb.x, h00); h00 = __fmaf_rn(av1.w, WHb.y, h00);
                h01 = __fmaf_rn(av1.z, WHb.z, h01); h01 = __fmaf_rn(av1.w, WHb.w, h01);
            }
        }

        // epilogues (identical arithmetic to validated version)
        {
            float v0 = __fadd_rn(__fadd_rn(xp2.x, a00), bh0c0);
            float v1 = __fadd_rn(__fadd_rn(xp2.y, a01), bh0c1);
            h0_out[oxy + 0] = xla_tanh(v0);
            h0_out[oxy + 1] = xla_tanh(v1);
            float u0 = __fadd_rn(__fadd_rn(c00, h00), cb1c0);
            float u1 = __fadd_rn(__fadd_rn(c01, h01), cb1c1);
            h1_out[oxy + 0] = xla_tanh(u0);
            h1_out[oxy + 1] = xla_tanh(u1);
        }

        grid_barrier();
    }
}

// ---------------- TF32 wmma logits, cp.async double-buffered -----------------
__global__ __launch_bounds__(256)
void logits_wmma(const float* __restrict__ H1all, const float* __restrict__ by1,
                 float* __restrict__ out)
{
    using namespace nvcuda;
    extern __shared__ float smd[];
    float* Asf = smd;                 // [2][128][36]
    float* Bsf = smd + 2*128*36;      // [2][128][36]

    const int tid  = threadIdx.x;
    const int wid  = tid >> 5;
    const int lane = tid & 31;
    const int bm = blockIdx.y * 128;
    const int bn = blockIdx.x * 128;
    const int wm = (wid >> 1) * 32;
    const int wn = (wid & 1) * 64;

    const int rr = tid >> 1;
    const int hf = (tid & 1) << 4;
    const uint32_t sbase = (uint32_t)__cvta_generic_to_shared(smd);

    wmma::fragment<wmma::accumulator, 16, 16, 8, float> acc[2][4];
    #pragma unroll
    for (int mi = 0; mi < 2; ++mi)
        #pragma unroll
        for (int ni = 0; ni < 4; ++ni)
            wmma::fill_fragment(acc[mi][ni], 0.f);

    const int NT = HID / 32;

    {
        const float* ga = H1all + (size_t)(bm + rr) * HID + hf;
        const float* gb = g_Wy1p + (size_t)(bn + rr) * HID + hf;
        uint32_t sa = sbase + (uint32_t)(((0*128 + rr)*36 + hf) * 4);
        uint32_t sb = sbase + (uint32_t)((2*128*36 + (0*128 + rr)*36 + hf) * 4);
        cp16(sa,      ga);      cp16(sa + 16, ga + 4);
        cp16(sa + 32, ga + 8);  cp16(sa + 48, ga + 12);
        cp16(sb,      gb);      cp16(sb + 16, gb + 4);
        cp16(sb + 32, gb + 8);  cp16(sb + 48, gb + 12);
        asm volatile("cp.async.commit_group;");
    }

    for (int it = 0; it < NT; ++it) {
        if (it + 1 < NT) {
            int s = (it + 1) & 1;
            int k0 = (it + 1) * 32;
            const float* ga = H1all + (size_t)(bm + rr) * HID + k0 + hf;
            const float* gb = g_Wy1p + (size_t)(bn + rr) * HID + k0 + hf;
            uint32_t sa = sbase + (uint32_t)(((s*128 + rr)*36 + hf) * 4);
            uint32_t sb = sbase + (uint32_t)((2*128*36 + (s*128 + rr)*36 + hf) * 4);
            cp16(sa,      ga);      cp16(sa + 16, ga + 4);
            cp16(sa + 32, ga + 8);  cp16(sa + 48, ga + 12);
            cp16(sb,      gb);      cp16(sb + 16, gb + 4);
            cp16(sb + 32, gb + 8);  cp16(sb + 48, gb + 12);
            asm volatile("cp.async.commit_group;");
            asm volatile("cp.async.wait_group 1;");
        } else {
            asm volatile("cp.async.wait_group 0;");
        }
        __syncthreads();

        const int s = it & 1;
        const float* Ab = Asf + (size_t)s * 128 * 36;
        const float* Bb = Bsf + (size_t)s * 128 * 36;

        #pragma unroll
        for (int ks = 0; ks < 32; ks += 8) {
            wmma::fragment<wmma::matrix_a, 16, 16, 8, wmma::precision::tf32, wmma::row_major> af[2];
            wmma::fragment<wmma::matrix_b, 16, 16, 8, wmma::precision::tf32, wmma::col_major> bf[4];
            #pragma unroll
            for (int mi = 0; mi < 2; ++mi) {
                wmma::load_matrix_sync(af[mi], Ab + (size_t)(wm + mi*16)*36 + ks, 36);
                #pragma unroll
                for (int e = 0; e < af[mi].num_elements; ++e)
                    af[mi].x[e] = wmma::__float_to_tf32(af[mi].x[e]);
            }
            #pragma unroll
            for (int ni = 0; ni < 4; ++ni) {
                wmma::load_matrix_sync(bf[ni], Bb + (size_t)(wn + ni*16)*36 + ks, 36);
                #pragma unroll
                for (int e = 0; e < bf[ni].num_elements; ++e)
                    bf[ni].x[e] = wmma::__float_to_tf32(bf[ni].x[e]);
            }
            #pragma unroll
            for (int mi = 0; mi < 2; ++mi)
                #pragma unroll
                for (int ni = 0; ni < 4; ++ni)
                    wmma::mma_sync(acc[mi][ni], af[mi], bf[ni], acc[mi][ni]);
        }
        __syncthreads();
    }

    float* st = smd + (size_t)wid * 320;
    #pragma unroll
    for (int mi = 0; mi < 2; ++mi)
        #pragma unroll
        for (int ni = 0; ni < 4; ++ni) {
            wmma::store_matrix_sync(st, acc[mi][ni], 20, wmma::mem_row_major);
            __syncwarp();
            #pragma unroll
            for (int e = 0; e < 8; ++e) {
                int idx = e * 32 + lane;
                int r2 = idx >> 4, c2 = idx & 15;
                int gr = bm + wm + mi*16 + r2;
                int gc = bn + wn + ni*16 + c2;
                if (gc < VOCAB)
                    out[(size_t)gr * VOCAB + gc] = __fadd_rn(st[r2*20 + c2], by1[gc]);
            }
            __syncwarp();
        }
}

// ---------------- small helper kernels ---------------------------------------
__global__ void pad_wy1_fix(const float* __restrict__ Wy1)
{
    size_t idx = (size_t)blockIdx.x * 256 + threadIdx.x;
    int n = (int)(idx >> 10);
    int k = (int)(idx & 1023);
    g_Wy1p[idx] = (n < VOCAB) ? Wy1[(size_t)n * HID + k] : 0.f;
}

__global__ void transpose_wy0(const float* __restrict__ Wy0)
{
    int idx = blockIdx.x * 256 + threadIdx.x;
    int j = idx >> 10, k = idx & 1023;
    g_Wy0T[(size_t)j * HID + k] = Wy0[(size_t)k * HID + j];
}

__global__ void tail(const float* __restrict__ h0f, const float* __restrict__ h1f,
                     float* __restrict__ out)
{
    int i = blockIdx.x * 256 + threadIdx.x;
    out[i]      = h0f[i];
    out[SB + i] = h1f[i];
}

// ---------------- launcher ---------------------------------------------------
extern "C" void kernel_launch(void* const* d_in, const int* in_sizes, int n_in,
                              void* d_out, int out_size)
{
    const int*   tok    = (const int*)  d_in[0];
    const float* hidden = (const float*)d_in[1];
    const float* emb    = (const float*)d_in[2];
    const float* Wx0    = (const float*)d_in[3];
    const float* Wh0    = (const float*)d_in[4];
    const float* bh0    = (const float*)d_in[5];
    const float* Wy0    = (const float*)d_in[6];
    const float* by0    = (const float*)d_in[7];
    const float* Wx1    = (const float*)d_in[8];
    const float* Wh1    = (const float*)d_in[9];
    const float* bh1    = (const float*)d_in[10];
    const float* Wy1    = (const float*)d_in[11];
    const float* by1    = (const float*)d_in[12];
    (void)in_sizes; (void)n_in;

    float *Xp, *H1, *h0, *WcP, *Wy0T;
    cudaGetSymbolAddress((void**)&Xp,   g_Xp);
    cudaGetSymbolAddress((void**)&H1,   g_H1);
    cudaGetSymbolAddress((void**)&h0,   g_h0);
    cudaGetSymbolAddress((void**)&WcP,  g_Wc);
    cudaGetSymbolAddress((void**)&Wy0T, g_Wy0T);

    const int SMEM_SCAN = 38408 * sizeof(float);               // 153632 B
    cudaFuncSetAttribute(scan_persistent,
                         cudaFuncAttributeMaxDynamicSharedMemorySize, SMEM_SCAN);
    const int SMEM_LOGITS = 2 * 2 * 128 * 36 * sizeof(float);  // 73728 B
    cudaFuncSetAttribute(logits_wmma,
                         cudaFuncAttributeMaxDynamicSharedMemorySize, SMEM_LOGITS);

    // (1) Xp = gather(emb, tok) @ Wx0^T   (raw, BIT-EXACT chain)
    gemm128<true><<<dim3(HID/128, TB/128), 256>>>(
        emb, Wx0, tok, Xp, TB, HID, HID);

    // (2) Wy0T ; (3) Wc = Wx1 @ Wy0   (tolerant h1 path)
    transpose_wy0<<<HID*HID/256, 256>>>(Wy0);
    gemm128<false><<<dim3(HID/128, HID/128), 256>>>(
        Wx1, Wy0T, nullptr, WcP, HID, HID, HID);

    // (4) persistent scan — fused init (state copy + cb1), all 128 steps
    scan_persistent<<<NCTA, 256, SMEM_SCAN>>>(Wh0, Wh1, bh0, Wx1, bh1, by0, hidden);

    // (5) pad Wy1 ; (6) logits = H1 @ Wy1^T + by1 (TF32 tensor cores)
    pad_wy1_fix<<<(NPAD*HID)/256, 256>>>(Wy1);
    logits_wmma<<<dim3(NPAD/128, TB/128), 256, SMEM_LOGITS>>>(H1, by1, (float*)d_out);

    // (7) final hidden states appended if out buffer includes them
    long total = (long)TB * VOCAB + 2L * SB;
    if ((long)out_size >= total)
        tail<<<SB/256, 256>>>(h0, H1 + (size_t)SEQ * SB,
                              (float*)d_out + (size_t)TB * VOCAB);
}